// round 2
// baseline (speedup 1.0000x reference)
#include <cuda_runtime.h>
#include <cuda_bf16.h>
#include <cstdint>

// ---------------- problem constants ----------------
#define BB 4096
#define VV 20
#define DD 768
#define MROWS (BB * VV)        // 81920
#define NN (2 * DD)            // 1536 interleaved (m1,m2)
#define KK DD                  // 768

// ---------------- scratch (static device globals; no allocations) ----------------
__device__ __nv_bfloat16 g_Xn[(size_t)MROWS * DD];   // softmaxed A, bf16 (126 MB)
__device__ __nv_bfloat16 g_Wc[(size_t)NN * DD];      // interleaved weights bf16 (2.4 MB)
__device__ float         g_Fused[(size_t)MROWS * DD];// relu(text*m1+m2) (252 MB)

// ---------------- baseline-PTX helpers (no sm_100a features) ----------------
__device__ __forceinline__ uint32_t smem_u32(const void* p) {
    uint32_t a;
    asm("{ .reg .u64 t; cvta.to.shared.u64 t, %1; cvt.u32.u64 %0, t; }" : "=r"(a) : "l"(p));
    return a;
}
__device__ __forceinline__ void cp_async16(uint32_t saddr, const void* gptr) {
    asm volatile("cp.async.cg.shared.global [%0], [%1], 16;\n" :: "r"(saddr), "l"(gptr));
}
#define CP_COMMIT() asm volatile("cp.async.commit_group;\n" ::: "memory")
#define CP_WAIT_1() asm volatile("cp.async.wait_group 1;\n" ::: "memory")
#define CP_WAIT_0() asm volatile("cp.async.wait_group 0;\n" ::: "memory")

__device__ __forceinline__ void ldsm_x4(uint32_t& r0, uint32_t& r1, uint32_t& r2, uint32_t& r3,
                                        uint32_t addr) {
    asm volatile("ldmatrix.sync.aligned.m8n8.x4.shared.b16 {%0,%1,%2,%3}, [%4];"
                 : "=r"(r0), "=r"(r1), "=r"(r2), "=r"(r3) : "r"(addr));
}
__device__ __forceinline__ void mma16816(float* c, const uint32_t* a, const uint32_t* b) {
    asm volatile(
        "mma.sync.aligned.m16n8k16.row.col.f32.bf16.bf16.f32 "
        "{%0,%1,%2,%3}, {%4,%5,%6,%7}, {%8,%9}, {%0,%1,%2,%3};"
        : "+f"(c[0]), "+f"(c[1]), "+f"(c[2]), "+f"(c[3])
        : "r"(a[0]), "r"(a[1]), "r"(a[2]), "r"(a[3]), "r"(b[0]), "r"(b[1]));
}

// ---------------- kernel 1: interleave + cast weights ----------------
// Wc[2e+p][k] = (p ? W2 : W1)[e][k], bf16
__global__ void prep_w(const float* __restrict__ W1, const float* __restrict__ W2) {
    int idx = blockIdx.x * blockDim.x + threadIdx.x;
    if (idx >= NN * DD) return;
    int n = idx / DD, k = idx - n * DD;
    int e = n >> 1;
    float v = (n & 1) ? W2[e * DD + k] : W1[e * DD + k];
    g_Wc[idx] = __float2bfloat16(v);
}

// ---------------- kernel 2: row softmax -> bf16 ----------------
__global__ void __launch_bounds__(256) softmax_rows(const float* __restrict__ vf) {
    int row = blockIdx.x;
    int tid = threadIdx.x;
    const float* x = vf + (size_t)row * DD;
    float a = x[tid], b = x[tid + 256], c = x[tid + 512];
    float m = fmaxf(a, fmaxf(b, c));
    #pragma unroll
    for (int o = 16; o; o >>= 1) m = fmaxf(m, __shfl_xor_sync(0xffffffffu, m, o));
    __shared__ float red[8];
    __shared__ float bc_max, bc_inv;
    int w = tid >> 5;
    if ((tid & 31) == 0) red[w] = m;
    __syncthreads();
    if (tid == 0) {
        float t = red[0];
        #pragma unroll
        for (int i = 1; i < 8; i++) t = fmaxf(t, red[i]);
        bc_max = t;
    }
    __syncthreads();
    float M_ = bc_max;
    float e0 = __expf(a - M_), e1 = __expf(b - M_), e2 = __expf(c - M_);
    float s = e0 + e1 + e2;
    #pragma unroll
    for (int o = 16; o; o >>= 1) s += __shfl_xor_sync(0xffffffffu, s, o);
    __syncthreads();
    if ((tid & 31) == 0) red[w] = s;
    __syncthreads();
    if (tid == 0) {
        float t = 0.f;
        #pragma unroll
        for (int i = 0; i < 8; i++) t += red[i];
        bc_inv = 1.f / t;
    }
    __syncthreads();
    float inv = bc_inv;
    __nv_bfloat16* dst = g_Xn + (size_t)row * DD;
    dst[tid]       = __float2bfloat16(e0 * inv);
    dst[tid + 256] = __float2bfloat16(e1 * inv);
    dst[tid + 512] = __float2bfloat16(e2 * inv);
}

// ---------------- kernel 3: HMMA GEMM + fused epilogue ----------------
// C[m][n] = sum_k Xn[m][k] * Wc[n][k]; epilogue relu(text*(m1+b1) + (m2+b2))
#define TM 128
#define TN 128
#define KC 64                              // 64 bf16 = 128B row, SW128-style swizzle
#define NKC (KK / KC)                      // 12
#define A_BYTES (TM * 128)                 // 16384
#define B_BYTES (TN * 128)                 // 16384
#define STAGE_BYTES (A_BYTES + B_BYTES)    // 32768
#define SM_TOTAL (2 * STAGE_BYTES)         // 65536

__device__ __forceinline__ uint32_t sw128(uint32_t off) {
    return off ^ ((off >> 3) & 0x70);
}

__device__ __forceinline__ void load_stage(uint32_t sbase, int s, int kc, int tid,
                                           const __nv_bfloat16* Ab, const __nv_bfloat16* Bw) {
    uint32_t abase = sbase + s * STAGE_BYTES;
    uint32_t bbase = abase + A_BYTES;
    // A tile: 128 rows x 128B (8 x 16B chunks/row) = 1024 chunks, 4/thread
    #pragma unroll
    for (int t = 0; t < 4; t++) {
        int idx = tid + t * 256;
        int r = idx >> 3, i = idx & 7;
        uint32_t off = (uint32_t)(r * 128 + i * 16);
        cp_async16(abase + sw128(off), (const char*)(Ab + (size_t)r * DD + kc * KC) + i * 16);
    }
    // B tile: 128 rows x 128B, 4/thread
    #pragma unroll
    for (int t = 0; t < 4; t++) {
        int idx = tid + t * 256;
        int r = idx >> 3, i = idx & 7;
        uint32_t off = (uint32_t)(r * 128 + i * 16);
        cp_async16(bbase + sw128(off), (const char*)(Bw + (size_t)r * DD + kc * KC) + i * 16);
    }
    CP_COMMIT();
}

__global__ void __launch_bounds__(256) gemm_kernel(const float* __restrict__ text,
                                                   const float* __restrict__ b1,
                                                   const float* __restrict__ b2) {
    extern __shared__ char smem[];
    uint32_t sbase = smem_u32(smem);
    int tid = threadIdx.x, wid = tid >> 5, lane = tid & 31;
    int mw = wid & 3, nw = wid >> 2;           // warp grid 4(m) x 2(n), warp tile 32x64
    int n0 = blockIdx.x * TN;                  // n fast -> A reuse across wave
    int m0 = blockIdx.y * TM;

    const __nv_bfloat16* Ab = g_Xn + (size_t)m0 * DD;
    const __nv_bfloat16* Bw = g_Wc + (size_t)n0 * DD;

    float acc[2][8][4];
    #pragma unroll
    for (int i = 0; i < 2; i++)
        #pragma unroll
        for (int j = 0; j < 8; j++)
            #pragma unroll
            for (int q = 0; q < 4; q++) acc[i][j][q] = 0.f;

    load_stage(sbase, 0, 0, tid, Ab, Bw);

    for (int c = 0; c < NKC; c++) {
        int s = c & 1;
        if (c + 1 < NKC) {
            load_stage(sbase, s ^ 1, c + 1, tid, Ab, Bw);
            CP_WAIT_1();
        } else {
            CP_WAIT_0();
        }
        __syncthreads();

        uint32_t abase = sbase + s * STAGE_BYTES;
        uint32_t bbase = abase + A_BYTES;
        #pragma unroll
        for (int ks = 0; ks < 4; ks++) {
            uint32_t a[2][4];
            #pragma unroll
            for (int mf = 0; mf < 2; mf++) {
                int row = mw * 32 + mf * 16 + (lane & 15);
                uint32_t off = (uint32_t)(row * 128 + ((lane >> 4) * 16) + ks * 32);
                ldsm_x4(a[mf][0], a[mf][1], a[mf][2], a[mf][3], abase + sw128(off));
            }
            uint32_t b[8][2];
            #pragma unroll
            for (int nf2 = 0; nf2 < 4; nf2++) {
                int nrow = nw * 64 + nf2 * 16 + (lane & 7) + (((lane >> 4) & 1) << 3);
                uint32_t off = (uint32_t)(nrow * 128 + (((lane >> 3) & 1) * 16) + ks * 32);
                uint32_t r0, r1, r2, r3;
                ldsm_x4(r0, r1, r2, r3, bbase + sw128(off));
                b[nf2 * 2][0] = r0;     b[nf2 * 2][1] = r1;
                b[nf2 * 2 + 1][0] = r2; b[nf2 * 2 + 1][1] = r3;
            }
            #pragma unroll
            for (int mf = 0; mf < 2; mf++)
                #pragma unroll
                for (int nf = 0; nf < 8; nf++)
                    mma16816(acc[mf][nf], a[mf], b[nf]);
        }
        __syncthreads();
    }

    // Fused epilogue, all register-local:
    // acc cols are interleaved (even n = m1, odd n = m2); c0/c1 and c2/c3 are
    // exactly the (m1[e], m2[e]) pair for one e per thread.
    #pragma unroll
    for (int mf = 0; mf < 2; mf++) {
        int m_a = m0 + mw * 32 + mf * 16 + (lane >> 2);   // rows for c0,c1
        int m_b = m_a + 8;                                 // rows for c2,c3
        const float* trow_a = text + (size_t)(m_a / VV) * DD;
        const float* trow_b = text + (size_t)(m_b / VV) * DD;
        #pragma unroll
        for (int nf = 0; nf < 8; nf++) {
            int e = ((n0 + nw * 64 + nf * 8) >> 1) + (lane & 3);
            float bb1 = __ldg(b1 + e), bb2 = __ldg(b2 + e);
            float va = fmaxf(fmaf(__ldg(trow_a + e), acc[mf][nf][0] + bb1,
                                  acc[mf][nf][1] + bb2), 0.f);
            float vb = fmaxf(fmaf(__ldg(trow_b + e), acc[mf][nf][2] + bb1,
                                  acc[mf][nf][3] + bb2), 0.f);
            g_Fused[(size_t)m_a * DD + e] = va;
            g_Fused[(size_t)m_b * DD + e] = vb;
        }
    }
}

// ---------------- kernel 4: conv3 -> relu -> conv3, per row ----------------
__global__ void __launch_bounds__(256) conv_kernel(const float* __restrict__ cw1,
                                                   const float* __restrict__ cb1,
                                                   const float* __restrict__ cw2,
                                                   const float* __restrict__ cb2,
                                                   float* __restrict__ out) {
    __shared__ float s1[DD];
    __shared__ float s2[DD];
    int row = blockIdx.x, tid = threadIdx.x;
    const float* src = g_Fused + (size_t)row * DD;
    float w10 = __ldg(cw1), w11 = __ldg(cw1 + 1), w12 = __ldg(cw1 + 2), bb1 = __ldg(cb1);
    float w20 = __ldg(cw2), w21 = __ldg(cw2 + 1), w22 = __ldg(cw2 + 2), bb2 = __ldg(cb2);
    s1[tid] = src[tid]; s1[tid + 256] = src[tid + 256]; s1[tid + 512] = src[tid + 512];
    __syncthreads();
    #pragma unroll
    for (int t = 0; t < 3; t++) {
        int i = tid + t * 256;
        float l = (i > 0)      ? s1[i - 1] : 0.f;
        float r = (i < DD - 1) ? s1[i + 1] : 0.f;
        s2[i] = fmaxf(w10 * l + w11 * s1[i] + w12 * r + bb1, 0.f);
    }
    __syncthreads();
    float* dst = out + (size_t)row * DD;
    #pragma unroll
    for (int t = 0; t < 3; t++) {
        int i = tid + t * 256;
        float l = (i > 0)      ? s2[i - 1] : 0.f;
        float r = (i < DD - 1) ? s2[i + 1] : 0.f;
        dst[i] = w20 * l + w21 * s2[i] + w22 * r + bb2;
    }
}

// ---------------- launch ----------------
extern "C" void kernel_launch(void* const* d_in, const int* in_sizes, int n_in,
                              void* d_out, int out_size) {
    const float* text = (const float*)d_in[0];
    const float* vf   = (const float*)d_in[1];
    const float* W1   = (const float*)d_in[2];
    const float* b1   = (const float*)d_in[3];
    const float* W2   = (const float*)d_in[4];
    const float* b2   = (const float*)d_in[5];
    const float* cw1  = (const float*)d_in[6];
    const float* cb1  = (const float*)d_in[7];
    const float* cw2  = (const float*)d_in[8];
    const float* cb2  = (const float*)d_in[9];
    float* out = (float*)d_out;

    cudaFuncSetAttribute(gemm_kernel, cudaFuncAttributeMaxDynamicSharedMemorySize, SM_TOTAL);

    prep_w<<<(NN * DD + 255) / 256, 256>>>(W1, W2);
    softmax_rows<<<MROWS, 256>>>(vf);
    gemm_kernel<<<dim3(NN / TN, MROWS / TM), 256, SM_TOTAL>>>(text, b1, b2);
    conv_kernel<<<MROWS, 256>>>(cw1, cb1, cw2, cb2, out);
}